// round 1
// baseline (speedup 1.0000x reference)
#include <cuda_runtime.h>
#include <cuda_bf16.h>
#include <cstdint>
#include <cstdio>

// ---------------------------------------------------------------------------
// Problem constants (fixed shapes from reference):
//   B=2, C=256, Im 768x1280, strides {4,8,16,32}, N=1024 rois
//   pooled 7x7, sampling grid 14x14, pool5 dim D = 256*49 = 12544
//   fc1: 12544->1024 relu, fc2: 1024->1024 relu, proj: 1024->20
// ---------------------------------------------------------------------------

#define NCH 256

// NHWC scratch for the 4 FPN levels (sum of B*H*W*C per level)
__device__ float g_nhwc[41779200];
__device__ float g_pool5[1024 * 12544];
__device__ float g_fc1[1024 * 1024];
__device__ float g_fc2[1024 * 1024];

__constant__ size_t c_lvl_off[4] = {0, 31457280, 39321600, 41287680};

// ---------------------------------------------------------------------------
// NCHW -> NHWC transpose (per batch: [C, HW] -> [HW, C]), tiled 32x32
// ---------------------------------------------------------------------------
__global__ void nchw2nhwc_kernel(const float* __restrict__ in, int HW, size_t off) {
    __shared__ float tile[32][33];
    int b = blockIdx.z;
    int hw0 = blockIdx.x * 32;
    int c0 = blockIdx.y * 32;

    const float* ip = in + ((size_t)b * NCH + c0) * HW + hw0;
#pragma unroll
    for (int i = 0; i < 32; i += 8)
        tile[threadIdx.y + i][threadIdx.x] = ip[(size_t)(threadIdx.y + i) * HW + threadIdx.x];
    __syncthreads();

    float* op = g_nhwc + off + ((size_t)b * HW + hw0) * NCH + c0;
#pragma unroll
    for (int i = 0; i < 32; i += 8)
        op[(size_t)(threadIdx.y + i) * NCH + threadIdx.x] = tile[threadIdx.x][threadIdx.y + i];
}

// ---------------------------------------------------------------------------
// ROIAlign (aligned=True, sampling_ratio=2, 7x7 out) with FPN level select.
// One block per roi, 256 threads = 256 channels. Stages the 12544-float row
// in dynamic smem so the global write is coalesced.
// ---------------------------------------------------------------------------
__global__ void roi_align_kernel(const float* __restrict__ rois) {
    extern __shared__ float shbuf[];  // 12544 floats
    __shared__ int   s_ix0[14], s_ix1[14], s_iy0[14], s_iy1[14];
    __shared__ float s_wx0[14], s_wx1[14], s_wy0[14], s_wy1[14];

    int n = blockIdx.x;
    int tid = threadIdx.x;

    const float* r = rois + (size_t)n * 5;
    int   b  = (int)r[0];
    float x1 = r[1], y1 = r[2], x2 = r[3], y2 = r[4];

    float w = x2 - x1, h = y2 - y1;
    float kf = floorf(4.0f + log2f(sqrtf(fmaxf(w * h, 1e-6f)) / 224.0f));
    kf = fminf(fmaxf(kf, 2.0f), 5.0f);
    int lvl = (int)kf - 2;

    float stride = (float)(4 << lvl);
    int H = 768 >> (lvl + 2);
    int W = 1280 >> (lvl + 2);
    const float* base = g_nhwc + c_lvl_off[lvl] + ((size_t)b * H * W) * NCH;

    if (tid < 28) {
        bool isx = tid < 14;
        int  s   = isx ? tid : tid - 14;
        float lo = isx ? x1 : y1;
        float hi = isx ? x2 : y2;
        int size = isx ? W : H;

        float a = lo / stride - 0.5f;
        float bb = hi / stride - 0.5f;
        float coord = a + (bb - a) * (((float)s + 0.5f) / 14.0f);
        float valid = (coord > -1.0f && coord < (float)size) ? 1.0f : 0.0f;
        float cc = fminf(fmaxf(coord, 0.0f), (float)(size - 1));
        int i0 = (int)floorf(cc);
        int i1 = min(i0 + 1, size - 1);
        float frac = cc - (float)i0;
        if (isx) {
            s_ix0[s] = i0; s_ix1[s] = i1;
            s_wx0[s] = (1.0f - frac) * valid; s_wx1[s] = frac * valid;
        } else {
            s_iy0[s] = i0; s_iy1[s] = i1;
            s_wy0[s] = (1.0f - frac) * valid; s_wy1[s] = frac * valid;
        }
    }
    __syncthreads();

    const float* bc = base + tid;  // this thread's channel

    for (int by = 0; by < 7; by++) {
        for (int bx = 0; bx < 7; bx++) {
            float acc = 0.0f;
#pragma unroll
            for (int i = 0; i < 2; i++) {
                int sy = by * 2 + i;
                float wy0 = s_wy0[sy], wy1 = s_wy1[sy];
                int row0 = s_iy0[sy] * W;
                int row1 = s_iy1[sy] * W;
#pragma unroll
                for (int j = 0; j < 2; j++) {
                    int sx = bx * 2 + j;
                    float wx0 = s_wx0[sx], wx1 = s_wx1[sx];
                    int xa = s_ix0[sx], xb = s_ix1[sx];
                    float v00 = __ldg(bc + (size_t)(row0 + xa) * NCH);
                    float v01 = __ldg(bc + (size_t)(row0 + xb) * NCH);
                    float v10 = __ldg(bc + (size_t)(row1 + xa) * NCH);
                    float v11 = __ldg(bc + (size_t)(row1 + xb) * NCH);
                    acc += wy0 * (wx0 * v00 + wx1 * v01) + wy1 * (wx0 * v10 + wx1 * v11);
                }
            }
            shbuf[tid * 49 + by * 7 + bx] = acc * 0.25f;
        }
    }
    __syncthreads();

    float* dst = g_pool5 + (size_t)n * 12544;
    for (int i = tid; i < 12544; i += 256) dst[i] = shbuf[i];
}

// ---------------------------------------------------------------------------
// SGEMM: C[M,N] = A[M,K] * B[N,K]^T + bias, optional ReLU.
// 64x64 tile, BK=16, 256 threads, 4x4 micro-tile. M,N % 64 == 0, K % 16 == 0.
// ---------------------------------------------------------------------------
template <bool RELU>
__global__ void gemm_tn_kernel(const float* __restrict__ A,
                               const float* __restrict__ B,
                               const float* __restrict__ bias,
                               float* __restrict__ C,
                               int M, int N, int K) {
    const int BM = 64, BN = 64, BK = 16;
    __shared__ float As[BK][BM + 1];
    __shared__ float Bs[BK][BN + 1];

    int tid = threadIdx.x;  // 256
    int bm = blockIdx.y * BM;
    int bn = blockIdx.x * BN;

    int lr = tid >> 2;          // 0..63
    int lk = (tid & 3) << 2;    // 0,4,8,12

    const float* Aptr = A + (size_t)(bm + lr) * K + lk;
    const float* Bptr = B + (size_t)(bn + lr) * K + lk;

    int tr = (tid >> 4) << 2;   // 0..60 step 4
    int tc = (tid & 15) << 2;   // 0..60 step 4

    float acc[4][4] = {};

    for (int k0 = 0; k0 < K; k0 += BK) {
        float4 a = *(const float4*)(Aptr + k0);
        float4 b = *(const float4*)(Bptr + k0);
        As[lk + 0][lr] = a.x; As[lk + 1][lr] = a.y;
        As[lk + 2][lr] = a.z; As[lk + 3][lr] = a.w;
        Bs[lk + 0][lr] = b.x; Bs[lk + 1][lr] = b.y;
        Bs[lk + 2][lr] = b.z; Bs[lk + 3][lr] = b.w;
        __syncthreads();

#pragma unroll
        for (int k = 0; k < BK; k++) {
            float ra[4], rb[4];
#pragma unroll
            for (int i = 0; i < 4; i++) ra[i] = As[k][tr + i];
#pragma unroll
            for (int j = 0; j < 4; j++) rb[j] = Bs[k][tc + j];
#pragma unroll
            for (int i = 0; i < 4; i++)
#pragma unroll
                for (int j = 0; j < 4; j++)
                    acc[i][j] += ra[i] * rb[j];
        }
        __syncthreads();
    }

#pragma unroll
    for (int i = 0; i < 4; i++) {
#pragma unroll
        for (int j = 0; j < 4; j++) {
            float v = acc[i][j] + bias[bn + tc + j];
            if (RELU) v = fmaxf(v, 0.0f);
            C[(size_t)(bm + tr + i) * N + bn + tc + j] = v;
        }
    }
}

// ---------------------------------------------------------------------------
// Final projection: out[n, j] = dot(fc2[n,:], p_w[j,:]) + p_b[j], j < 20
// ---------------------------------------------------------------------------
__global__ void proj_kernel(const float* __restrict__ fc2,
                            const float* __restrict__ p_w,
                            const float* __restrict__ p_b,
                            float* __restrict__ out, int NJ) {
    __shared__ float sh[1024];
    int n = blockIdx.x;
    for (int i = threadIdx.x; i < 1024; i += blockDim.x)
        sh[i] = fc2[(size_t)n * 1024 + i];
    __syncthreads();
    int j = threadIdx.x;
    if (j < NJ) {
        const float* wrow = p_w + (size_t)j * 1024;
        float s = p_b[j];
#pragma unroll 8
        for (int k = 0; k < 1024; k++) s += sh[k] * wrow[k];
        out[(size_t)n * NJ + j] = s;
    }
}

// ---------------------------------------------------------------------------
extern "C" void kernel_launch(void* const* d_in, const int* in_sizes, int n_in,
                              void* d_out, int out_size) {
    const float* fm0   = (const float*)d_in[0];
    const float* fm1   = (const float*)d_in[1];
    const float* fm2   = (const float*)d_in[2];
    const float* fm3   = (const float*)d_in[3];
    const float* rois  = (const float*)d_in[4];
    const float* fc1_w = (const float*)d_in[5];
    const float* fc1_b = (const float*)d_in[6];
    const float* fc2_w = (const float*)d_in[7];
    const float* fc2_b = (const float*)d_in[8];
    const float* p_w   = (const float*)d_in[9];
    const float* p_b   = (const float*)d_in[10];
    float* out = (float*)d_out;

    int nrois = in_sizes[4] / 5;        // 1024
    int nj = out_size / nrois;          // 20

    // NCHW -> NHWC for the 4 FPN levels
    nchw2nhwc_kernel<<<dim3(61440 / 32, 8, 2), dim3(32, 8)>>>(fm0, 61440, (size_t)0);
    nchw2nhwc_kernel<<<dim3(15360 / 32, 8, 2), dim3(32, 8)>>>(fm1, 15360, (size_t)31457280);
    nchw2nhwc_kernel<<<dim3(3840 / 32, 8, 2), dim3(32, 8)>>>(fm2, 3840, (size_t)39321600);
    nchw2nhwc_kernel<<<dim3(960 / 32, 8, 2), dim3(32, 8)>>>(fm3, 960, (size_t)41287680);

    // ROIAlign (needs 50176 B dynamic smem)
    cudaFuncSetAttribute(roi_align_kernel,
                         cudaFuncAttributeMaxDynamicSharedMemorySize, 50176);
    roi_align_kernel<<<nrois, 256, 50176>>>(rois);

    float *pool5p, *fc1p, *fc2p;
    cudaGetSymbolAddress((void**)&pool5p, g_pool5);
    cudaGetSymbolAddress((void**)&fc1p, g_fc1);
    cudaGetSymbolAddress((void**)&fc2p, g_fc2);

    // FC1: [N,12544] @ [1024,12544]^T + b, relu
    gemm_tn_kernel<true><<<dim3(1024 / 64, nrois / 64), 256>>>(
        pool5p, fc1_w, fc1_b, fc1p, nrois, 1024, 12544);
    // FC2: [N,1024] @ [1024,1024]^T + b, relu
    gemm_tn_kernel<true><<<dim3(1024 / 64, nrois / 64), 256>>>(
        fc1p, fc2_w, fc2_b, fc2p, nrois, 1024, 1024);
    // Projection: [N,1024] @ [20,1024]^T + b
    proj_kernel<<<nrois, 256>>>(fc2p, p_w, p_b, out, nj);
}

// round 3
// speedup vs baseline: 3.0114x; 3.0114x over previous
#include <cuda_runtime.h>
#include <cuda_bf16.h>
#include <cstdint>

// ---------------------------------------------------------------------------
// Shapes: B=2, C=256, Im 768x1280, strides {4,8,16,32}, N=1024 rois
// pool5 D = 256*49 = 12544; fc1: 12544->1024 relu; fc2: 1024->1024 relu; proj->20
// ---------------------------------------------------------------------------

#define NCH 256

// tcgen05 is arch-specific (sm_103a). The harness also runs a baseline
// compute_103 ptxas pass where those instructions are illegal, so every
// tcgen05 usage is gated on the arch-feature macro; the baseline pass gets a
// correct SIMT fallback instead.
#if defined(__CUDA_ARCH__) && defined(__CUDA_ARCH_FEAT_SM103_ALL)
#define HAS_TCGEN05 1
#else
#define HAS_TCGEN05 0
#endif

__device__ float g_nhwc[41779200];
__device__ __nv_bfloat16 g_p5_hi[1024 * 12544];
__device__ __nv_bfloat16 g_p5_lo[1024 * 12544];
__device__ __nv_bfloat16 g_w1_hi[1024 * 12544];
__device__ __nv_bfloat16 g_w1_lo[1024 * 12544];
__device__ __nv_bfloat16 g_fc1_hi[1024 * 1024];
__device__ __nv_bfloat16 g_fc1_lo[1024 * 1024];
__device__ __nv_bfloat16 g_w2_hi[1024 * 1024];
__device__ __nv_bfloat16 g_w2_lo[1024 * 1024];
__device__ float g_fc2[1024 * 1024];

__constant__ size_t c_lvl_off[4] = {0, 31457280, 39321600, 41287680};

// ============================ PTX helpers ==================================
__device__ __forceinline__ uint32_t smem_u32(const void* p) {
    uint32_t a;
    asm("{ .reg .u64 t; cvta.to.shared.u64 t, %1; cvt.u32.u64 %0, t; }" : "=r"(a) : "l"(p));
    return a;
}
__device__ __forceinline__ uint32_t elect_one() {
    uint32_t p;
    asm volatile("{\n\t.reg .pred p;\n\telect.sync _|p, 0xFFFFFFFF;\n\tselp.b32 %0, 1, 0, p;\n\t}" : "=r"(p));
    return p;
}
#define MBARRIER_INIT(addr, cnt) \
    asm volatile("mbarrier.init.shared.b64 [%0], %1;" :: "r"(addr), "r"(cnt) : "memory")
#define MBARRIER_WAIT_PARITY(addr, par) do {                                          \
    uint32_t _m = (addr); uint32_t _p = (par); uint32_t _d;                           \
    asm volatile("{\n\t.reg .pred p;\n\t"                                             \
        "mbarrier.try_wait.parity.acquire.cta.shared::cta.b64 p, [%1], %2;\n\t"       \
        "selp.b32 %0, 1, 0, p;\n\t}" : "=r"(_d) : "r"(_m), "r"(_p) : "memory");       \
    if (!_d) {                                                                        \
        asm volatile("{\n\t.reg .pred P1;\n\t"                                        \
            "WL_%=:\n\t"                                                              \
            "mbarrier.try_wait.parity.acquire.cta.shared::cta.b64 P1, [%0], %1, 0x989680;\n\t" \
            "@P1 bra.uni WD_%=;\n\tbra.uni WL_%=;\n\tWD_%=:\n\t}"                     \
            :: "r"(_m), "r"(_p) : "memory");                                          \
    } } while (0)
#define FENCE_PROXY_ASYNC() asm volatile("fence.proxy.async.shared::cta;" ::: "memory")
#define CP_COMMIT() asm volatile("cp.async.commit_group;" ::: "memory")
#define CP_WAIT_1() asm volatile("cp.async.wait_group 1;" ::: "memory")

#if HAS_TCGEN05
#define TCGEN05_ALLOC(sa, n) \
    asm volatile("tcgen05.alloc.cta_group::1.sync.aligned.shared::cta.b32 [%0], %1;" :: "r"(sa), "r"(n) : "memory")
#define TCGEN05_DEALLOC(t, n) \
    asm volatile("tcgen05.dealloc.cta_group::1.sync.aligned.b32 %0, %1;" :: "r"(t), "r"(n))
#define TCGEN05_RELINQ() \
    asm volatile("tcgen05.relinquish_alloc_permit.cta_group::1.sync.aligned;")
#define TCGEN05_COMMIT(mb) \
    asm volatile("tcgen05.commit.cta_group::1.mbarrier::arrive::one.shared::cluster.b64 [%0];" :: "r"(mb) : "memory")
#define TCGEN05_FENCE_AFTER()  asm volatile("tcgen05.fence::after_thread_sync;" ::: "memory")
#define TCGEN05_FENCE_BEFORE() asm volatile("tcgen05.fence::before_thread_sync;" ::: "memory")
#define TCGEN05_WAIT_LD() asm volatile("tcgen05.wait::ld.sync.aligned;" ::: "memory")

#define TCGEN05_LD_X32(r, ta)                                                          \
    asm volatile("tcgen05.ld.sync.aligned.32x32b.x32.b32 "                             \
        "{%0, %1, %2, %3, %4, %5, %6, %7, %8, %9, %10, %11, %12, %13, %14, %15, "      \
        " %16, %17, %18, %19, %20, %21, %22, %23, %24, %25, %26, %27, %28, %29, %30, %31}, [%32];" \
        : "=r"((r)[0]), "=r"((r)[1]), "=r"((r)[2]), "=r"((r)[3]),                      \
          "=r"((r)[4]), "=r"((r)[5]), "=r"((r)[6]), "=r"((r)[7]),                      \
          "=r"((r)[8]), "=r"((r)[9]), "=r"((r)[10]), "=r"((r)[11]),                    \
          "=r"((r)[12]), "=r"((r)[13]), "=r"((r)[14]), "=r"((r)[15]),                  \
          "=r"((r)[16]), "=r"((r)[17]), "=r"((r)[18]), "=r"((r)[19]),                  \
          "=r"((r)[20]), "=r"((r)[21]), "=r"((r)[22]), "=r"((r)[23]),                  \
          "=r"((r)[24]), "=r"((r)[25]), "=r"((r)[26]), "=r"((r)[27]),                  \
          "=r"((r)[28]), "=r"((r)[29]), "=r"((r)[30]), "=r"((r)[31])                   \
        : "r"(ta))

__device__ __forceinline__ void mma_f16_ss(uint32_t d, uint64_t a, uint64_t b,
                                           uint32_t idesc, bool en) {
    uint32_t e = en ? 1u : 0u;
    asm volatile(
        "{\n\t.reg .pred p;\n\tsetp.ne.u32 p, %4, 0;\n\t"
        "tcgen05.mma.cta_group::1.kind::f16 [%0], %1, %2, %3, {%5, %5, %5, %5}, p;\n\t}"
        :: "r"(d), "l"(a), "l"(b), "r"(idesc), "r"(e), "r"(0u) : "memory");
}
#endif  // HAS_TCGEN05

// SW128 K-major descriptor: layout=2, version=1, SBO=64, LBO=1
static constexpr uint64_t DESC_BASE_SW128 =
    (uint64_t(2) << 61) | (uint64_t(1) << 46) | (uint64_t(64) << 32) | (uint64_t(1) << 16);
#define MAKE_DESC(a) (DESC_BASE_SW128 | ((uint64_t)((a) >> 4) & 0x3FFF))

// idesc kind::f16: F32 accum, BF16 a/b, M=128, N=128
static constexpr uint32_t GEMM_IDESC =
    (1u << 4) | (1u << 7) | (1u << 10) | ((128u / 8u) << 17) | ((128u / 16u) << 24);

__device__ __forceinline__ void pack_hi_lo(float v0, float v1, uint32_t& h, uint32_t& l) {
    asm("cvt.rn.bf16x2.f32 %0, %1, %2;" : "=r"(h) : "f"(v1), "f"(v0));
    float l0 = v0 - __uint_as_float(h << 16);
    float l1 = v1 - __uint_as_float(h & 0xffff0000u);
    asm("cvt.rn.bf16x2.f32 %0, %1, %2;" : "=r"(l) : "f"(l1), "f"(l0));
}

// ---------------------------------------------------------------------------
// NCHW -> NHWC transpose, tiled 32x32
// ---------------------------------------------------------------------------
__global__ void nchw2nhwc_kernel(const float* __restrict__ in, int HW, size_t off) {
    __shared__ float tile[32][33];
    int b = blockIdx.z;
    int hw0 = blockIdx.x * 32;
    int c0 = blockIdx.y * 32;
    const float* ip = in + ((size_t)b * NCH + c0) * HW + hw0;
#pragma unroll
    for (int i = 0; i < 32; i += 8)
        tile[threadIdx.y + i][threadIdx.x] = ip[(size_t)(threadIdx.y + i) * HW + threadIdx.x];
    __syncthreads();
    float* op = g_nhwc + off + ((size_t)b * HW + hw0) * NCH + c0;
#pragma unroll
    for (int i = 0; i < 32; i += 8)
        op[(size_t)(threadIdx.y + i) * NCH + threadIdx.x] = tile[threadIdx.x][threadIdx.y + i];
}

// ---------------------------------------------------------------------------
// ROIAlign: one block per roi, 256 threads = channels; writes hi/lo bf16 rows.
// ---------------------------------------------------------------------------
__global__ void roi_align_kernel(const float* __restrict__ rois) {
    extern __shared__ float shbuf[];  // 12544 floats
    __shared__ int   s_ix0[14], s_ix1[14], s_iy0[14], s_iy1[14];
    __shared__ float s_wx0[14], s_wx1[14], s_wy0[14], s_wy1[14];

    int n = blockIdx.x;
    int tid = threadIdx.x;

    const float* r = rois + (size_t)n * 5;
    int   b  = (int)r[0];
    float x1 = r[1], y1 = r[2], x2 = r[3], y2 = r[4];

    float w = x2 - x1, h = y2 - y1;
    float kf = floorf(4.0f + log2f(sqrtf(fmaxf(w * h, 1e-6f)) / 224.0f));
    kf = fminf(fmaxf(kf, 2.0f), 5.0f);
    int lvl = (int)kf - 2;

    float stride = (float)(4 << lvl);
    int H = 768 >> (lvl + 2);
    int W = 1280 >> (lvl + 2);
    const float* base = g_nhwc + c_lvl_off[lvl] + ((size_t)b * H * W) * NCH;

    if (tid < 28) {
        bool isx = tid < 14;
        int  s   = isx ? tid : tid - 14;
        float lo = isx ? x1 : y1;
        float hi = isx ? x2 : y2;
        int size = isx ? W : H;
        float a = lo / stride - 0.5f;
        float bb = hi / stride - 0.5f;
        float coord = a + (bb - a) * (((float)s + 0.5f) / 14.0f);
        float valid = (coord > -1.0f && coord < (float)size) ? 1.0f : 0.0f;
        float cc = fminf(fmaxf(coord, 0.0f), (float)(size - 1));
        int i0 = (int)floorf(cc);
        int i1 = min(i0 + 1, size - 1);
        float frac = cc - (float)i0;
        if (isx) { s_ix0[s] = i0; s_ix1[s] = i1; s_wx0[s] = (1.0f - frac) * valid; s_wx1[s] = frac * valid; }
        else     { s_iy0[s] = i0; s_iy1[s] = i1; s_wy0[s] = (1.0f - frac) * valid; s_wy1[s] = frac * valid; }
    }
    __syncthreads();

    const float* bc = base + tid;
    for (int by = 0; by < 7; by++) {
        for (int bx = 0; bx < 7; bx++) {
            float acc = 0.0f;
#pragma unroll
            for (int i = 0; i < 2; i++) {
                int sy = by * 2 + i;
                float wy0 = s_wy0[sy], wy1 = s_wy1[sy];
                int row0 = s_iy0[sy] * W;
                int row1 = s_iy1[sy] * W;
#pragma unroll
                for (int j = 0; j < 2; j++) {
                    int sx = bx * 2 + j;
                    float wx0 = s_wx0[sx], wx1 = s_wx1[sx];
                    int xa = s_ix0[sx], xb = s_ix1[sx];
                    float v00 = __ldg(bc + (size_t)(row0 + xa) * NCH);
                    float v01 = __ldg(bc + (size_t)(row0 + xb) * NCH);
                    float v10 = __ldg(bc + (size_t)(row1 + xa) * NCH);
                    float v11 = __ldg(bc + (size_t)(row1 + xb) * NCH);
                    acc += wy0 * (wx0 * v00 + wx1 * v01) + wy1 * (wx0 * v10 + wx1 * v11);
                }
            }
            shbuf[tid * 49 + by * 7 + bx] = acc * 0.25f;
        }
    }
    __syncthreads();

    uint32_t* hd = (uint32_t*)(g_p5_hi + (size_t)n * 12544);
    uint32_t* ld = (uint32_t*)(g_p5_lo + (size_t)n * 12544);
    for (int i = tid; i < 6272; i += 256) {
        float v0 = shbuf[2 * i], v1 = shbuf[2 * i + 1];
        uint32_t hh, ll;
        pack_hi_lo(v0, v1, hh, ll);
        hd[i] = hh; ld[i] = ll;
    }
}

// ---------------------------------------------------------------------------
// fp32 -> bf16 hi/lo split (for weights)
// ---------------------------------------------------------------------------
__global__ void split_kernel(const float* __restrict__ in,
                             __nv_bfloat16* __restrict__ hi,
                             __nv_bfloat16* __restrict__ lo, int n4) {
    int i = blockIdx.x * blockDim.x + threadIdx.x;
    if (i >= n4) return;
    float4 v = ((const float4*)in)[i];
    uint32_t h0, h1, l0, l1;
    pack_hi_lo(v.x, v.y, h0, l0);
    pack_hi_lo(v.z, v.w, h1, l1);
    ((uint2*)hi)[i] = make_uint2(h0, h1);
    ((uint2*)lo)[i] = make_uint2(l0, l1);
}

// ---------------------------------------------------------------------------
// GEMM: C[M,N] = A[M,K] @ B[N,K]^T + bias, ReLU.
// A,B given as bf16 hi/lo pairs. sm_103a pass: tcgen05, D = Ah*Bh+Ah*Bl+Al*Bh.
// Baseline pass (fallback, never selected on GB300 if 103a cubin exists):
// SIMT FFMA on reconstructed fp32.
// 128x128 tile, BK=64, 256 threads, cp.async double buffer.
// ---------------------------------------------------------------------------
__device__ __forceinline__ void load_tile16(uint32_t s_tile, const __nv_bfloat16* g,
                                            int ldK, int tid) {
#pragma unroll
    for (int q = 0; q < 4; q++) {
        int gid = tid + q * 256;
        int row = gid >> 3, c16 = gid & 7;
        uint32_t dst = s_tile + row * 128 + ((c16 ^ (row & 7)) << 4);
        const char* src = (const char*)(g + (size_t)row * ldK) + (c16 << 4);
        asm volatile("cp.async.cg.shared.global [%0], [%1], 16;" :: "r"(dst), "l"(src) : "memory");
    }
}

template <bool SPLIT_OUT>
__global__ __launch_bounds__(256, 1) void gemm_tc(
    const __nv_bfloat16* __restrict__ Ahi, const __nv_bfloat16* __restrict__ Alo,
    const __nv_bfloat16* __restrict__ Bhi, const __nv_bfloat16* __restrict__ Blo,
    const float* __restrict__ bias,
    float* __restrict__ Cf, __nv_bfloat16* __restrict__ Chi, __nv_bfloat16* __restrict__ Clo,
    int N, int K) {
    extern __shared__ char dsm[];
    int tid = threadIdx.x;
    int bm = blockIdx.y * 128, bn = blockIdx.x * 128;

#if HAS_TCGEN05
    __shared__ uint32_t s_tmem;
    __shared__ uint64_t s_mbar[2];

    uint32_t sbase = (smem_u32(dsm) + 1023u) & ~1023u;
    int wid = tid >> 5, lid = tid & 31;

    uint32_t mb0 = smem_u32(&s_mbar[0]);
    uint32_t mb1 = smem_u32(&s_mbar[1]);

    if (wid == 0) TCGEN05_ALLOC(smem_u32(&s_tmem), 128);
    if (tid == 0) { MBARRIER_INIT(mb0, 1); MBARRIER_INIT(mb1, 1); }
    __syncthreads();
    uint32_t tmem = s_tmem;
    if (wid == 0) TCGEN05_RELINQ();

    const int nblk = K >> 6;

    const __nv_bfloat16* Ah = Ahi + (size_t)bm * K;
    const __nv_bfloat16* Al = Alo + (size_t)bm * K;
    const __nv_bfloat16* Bh = Bhi + (size_t)bn * K;
    const __nv_bfloat16* Bl = Blo + (size_t)bn * K;

#pragma unroll
    for (int p = 0; p < 2; p++) {
        uint32_t st = sbase + p * 65536u;
        load_tile16(st,          Ah + p * 64, K, tid);
        load_tile16(st + 16384u, Al + p * 64, K, tid);
        load_tile16(st + 32768u, Bh + p * 64, K, tid);
        load_tile16(st + 49152u, Bl + p * 64, K, tid);
        CP_COMMIT();
    }

    int ph0 = 0, ph1 = 0;
    for (int i = 0; i < nblk; i++) {
        int s = i & 1;
        CP_WAIT_1();
        __syncthreads();
        if (tid < 32) {
            if (elect_one()) {
                FENCE_PROXY_ASYNC();
                uint32_t st = sbase + (uint32_t)s * 65536u;
                uint64_t dah = MAKE_DESC(st);
                uint64_t dal = MAKE_DESC(st + 16384u);
                uint64_t dbh = MAKE_DESC(st + 32768u);
                uint64_t dbl = MAKE_DESC(st + 49152u);
                bool en = (i > 0);
#pragma unroll
                for (int k = 0; k < 4; k++) {
                    mma_f16_ss(tmem, dah + k * 2, dbh + k * 2, GEMM_IDESC, en); en = true;
                    mma_f16_ss(tmem, dah + k * 2, dbl + k * 2, GEMM_IDESC, true);
                    mma_f16_ss(tmem, dal + k * 2, dbh + k * 2, GEMM_IDESC, true);
                }
                TCGEN05_COMMIT(s == 0 ? mb0 : mb1);
            }
        }
        if (s == 0) { MBARRIER_WAIT_PARITY(mb0, ph0); ph0 ^= 1; }
        else        { MBARRIER_WAIT_PARITY(mb1, ph1); ph1 ^= 1; }
        __syncthreads();
        if (i + 2 < nblk) {
            uint32_t st = sbase + (uint32_t)s * 65536u;
            int j = i + 2;
            load_tile16(st,          Ah + j * 64, K, tid);
            load_tile16(st + 16384u, Al + j * 64, K, tid);
            load_tile16(st + 32768u, Bh + j * 64, K, tid);
            load_tile16(st + 49152u, Bl + j * 64, K, tid);
        }
        CP_COMMIT();
    }

    __syncthreads();
    TCGEN05_FENCE_AFTER();

    if (tid < 128) {
        int row = bm + wid * 32 + lid;
#pragma unroll
        for (int cb = 0; cb < 128; cb += 32) {
            uint32_t rr[32];
            TCGEN05_LD_X32(rr, tmem + cb);
            TCGEN05_WAIT_LD();
            if (SPLIT_OUT) {
                uint32_t* hd = (uint32_t*)(Chi + (size_t)row * N + bn + cb);
                uint32_t* ld = (uint32_t*)(Clo + (size_t)row * N + bn + cb);
#pragma unroll
                for (int c = 0; c < 32; c += 2) {
                    float v0 = fmaxf(__uint_as_float(rr[c])     + bias[bn + cb + c],     0.0f);
                    float v1 = fmaxf(__uint_as_float(rr[c + 1]) + bias[bn + cb + c + 1], 0.0f);
                    uint32_t hh, ll;
                    pack_hi_lo(v0, v1, hh, ll);
                    hd[c >> 1] = hh; ld[c >> 1] = ll;
                }
            } else {
                float* cd = Cf + (size_t)row * N + bn + cb;
#pragma unroll
                for (int c = 0; c < 32; c++)
                    cd[c] = fmaxf(__uint_as_float(rr[c]) + bias[bn + cb + c], 0.0f);
            }
        }
        TCGEN05_FENCE_BEFORE();
    }
    __syncthreads();
    if (wid == 0) TCGEN05_DEALLOC(tmem, 128);

#else  // ---------------- SIMT fallback (baseline compute_103 pass) ---------
    // As/Bs tiles of reconstructed fp32 in dynamic smem: [16][128] each.
    float* As = (float*)dsm;
    float* Bs = As + 16 * 132;

    int tr = (tid >> 4) * 8;  // 0..120 step 8
    int tc = (tid & 15) * 8;

    float acc[8][8] = {};

    for (int k0 = 0; k0 < K; k0 += 16) {
        // 16x128 = 2048 elements each, 8 per thread
#pragma unroll
        for (int e = 0; e < 8; e++) {
            int idx = tid * 8 + e;
            int kk = idx >> 7, rr = idx & 127;
            As[kk * 132 + rr] = __bfloat162float(Ahi[(size_t)(bm + rr) * K + k0 + kk]) +
                                __bfloat162float(Alo[(size_t)(bm + rr) * K + k0 + kk]);
            Bs[kk * 132 + rr] = __bfloat162float(Bhi[(size_t)(bn + rr) * K + k0 + kk]) +
                                __bfloat162float(Blo[(size_t)(bn + rr) * K + k0 + kk]);
        }
        __syncthreads();
#pragma unroll
        for (int k = 0; k < 16; k++) {
            float ra[8], rb[8];
#pragma unroll
            for (int i = 0; i < 8; i++) ra[i] = As[k * 132 + tr + i];
#pragma unroll
            for (int j = 0; j < 8; j++) rb[j] = Bs[k * 132 + tc + j];
#pragma unroll
            for (int i = 0; i < 8; i++)
#pragma unroll
                for (int j = 0; j < 8; j++) acc[i][j] += ra[i] * rb[j];
        }
        __syncthreads();
    }

#pragma unroll
    for (int i = 0; i < 8; i++) {
#pragma unroll
        for (int j = 0; j < 8; j += 2) {
            float v0 = fmaxf(acc[i][j]     + bias[bn + tc + j],     0.0f);
            float v1 = fmaxf(acc[i][j + 1] + bias[bn + tc + j + 1], 0.0f);
            size_t o = (size_t)(bm + tr + i) * N + bn + tc + j;
            if (SPLIT_OUT) {
                uint32_t hh, ll;
                pack_hi_lo(v0, v1, hh, ll);
                *(uint32_t*)(Chi + o) = hh;
                *(uint32_t*)(Clo + o) = ll;
            } else {
                Cf[o] = v0; Cf[o + 1] = v1;
            }
        }
    }
#endif
}

// ---------------------------------------------------------------------------
// Final projection: out[n, j] = dot(fc2[n,:], p_w[j,:]) + p_b[j], j < 20
// ---------------------------------------------------------------------------
__global__ void proj_kernel(const float* __restrict__ fc2,
                            const float* __restrict__ p_w,
                            const float* __restrict__ p_b,
                            float* __restrict__ out, int NJ) {
    __shared__ float sh[1024];
    int n = blockIdx.x;
    for (int i = threadIdx.x; i < 1024; i += blockDim.x)
        sh[i] = fc2[(size_t)n * 1024 + i];
    __syncthreads();
    int j = threadIdx.x;
    if (j < NJ) {
        const float* wrow = p_w + (size_t)j * 1024;
        float s = p_b[j];
#pragma unroll 8
        for (int k = 0; k < 1024; k++) s += sh[k] * wrow[k];
        out[(size_t)n * NJ + j] = s;
    }
}

// ---------------------------------------------------------------------------
extern "C" void kernel_launch(void* const* d_in, const int* in_sizes, int n_in,
                              void* d_out, int out_size) {
    const float* fm0   = (const float*)d_in[0];
    const float* fm1   = (const float*)d_in[1];
    const float* fm2   = (const float*)d_in[2];
    const float* fm3   = (const float*)d_in[3];
    const float* rois  = (const float*)d_in[4];
    const float* fc1_w = (const float*)d_in[5];
    const float* fc1_b = (const float*)d_in[6];
    const float* fc2_w = (const float*)d_in[7];
    const float* fc2_b = (const float*)d_in[8];
    const float* p_w   = (const float*)d_in[9];
    const float* p_b   = (const float*)d_in[10];
    float* out = (float*)d_out;

    int nrois = in_sizes[4] / 5;   // 1024
    int nj = out_size / nrois;     // 20

    // NCHW -> NHWC
    nchw2nhwc_kernel<<<dim3(61440 / 32, 8, 2), dim3(32, 8)>>>(fm0, 61440, (size_t)0);
    nchw2nhwc_kernel<<<dim3(15360 / 32, 8, 2), dim3(32, 8)>>>(fm1, 15360, (size_t)31457280);
    nchw2nhwc_kernel<<<dim3(3840 / 32, 8, 2), dim3(32, 8)>>>(fm2, 3840, (size_t)39321600);
    nchw2nhwc_kernel<<<dim3(960 / 32, 8, 2), dim3(32, 8)>>>(fm3, 960, (size_t)41287680);

    // ROIAlign -> pool5 (bf16 hi/lo)
    cudaFuncSetAttribute(roi_align_kernel,
                         cudaFuncAttributeMaxDynamicSharedMemorySize, 50176);
    roi_align_kernel<<<nrois, 256, 50176>>>(rois);

    // Weight splits
    __nv_bfloat16 *w1h, *w1l, *w2h, *w2l, *p5h, *p5l, *f1h, *f1l;
    float* fc2p;
    cudaGetSymbolAddress((void**)&w1h, g_w1_hi);
    cudaGetSymbolAddress((void**)&w1l, g_w1_lo);
    cudaGetSymbolAddress((void**)&w2h, g_w2_hi);
    cudaGetSymbolAddress((void**)&w2l, g_w2_lo);
    cudaGetSymbolAddress((void**)&p5h, g_p5_hi);
    cudaGetSymbolAddress((void**)&p5l, g_p5_lo);
    cudaGetSymbolAddress((void**)&f1h, g_fc1_hi);
    cudaGetSymbolAddress((void**)&f1l, g_fc1_lo);
    cudaGetSymbolAddress((void**)&fc2p, g_fc2);

    split_kernel<<<(12544 * 1024 / 4 + 255) / 256, 256>>>(fc1_w, w1h, w1l, 12544 * 1024 / 4);
    split_kernel<<<(1024 * 1024 / 4 + 255) / 256, 256>>>(fc2_w, w2h, w2l, 1024 * 1024 / 4);

    // GEMMs
    const int GEMM_SMEM = 1024 + 2 * 4 * 16384;  // 132096
    cudaFuncSetAttribute(gemm_tc<true>,
                         cudaFuncAttributeMaxDynamicSharedMemorySize, GEMM_SMEM);
    cudaFuncSetAttribute(gemm_tc<false>,
                         cudaFuncAttributeMaxDynamicSharedMemorySize, GEMM_SMEM);

    // FC1: [1024, 12544] x [1024, 12544]^T -> fc1 hi/lo
    gemm_tc<true><<<dim3(8, nrois / 128), 256, GEMM_SMEM>>>(
        p5h, p5l, w1h, w1l, fc1_b, nullptr, f1h, f1l, 1024, 12544);
    // FC2: [1024, 1024] x [1024, 1024]^T -> fc2 fp32
    gemm_tc<false><<<dim3(8, nrois / 128), 256, GEMM_SMEM>>>(
        f1h, f1l, w2h, w2l, fc2_b, fc2p, nullptr, nullptr, 1024, 1024);

    // Projection
    proj_kernel<<<nrois, 256>>>(fc2p, p_w, p_b, out, nj);
}

// round 4
// speedup vs baseline: 3.2056x; 1.0645x over previous
#include <cuda_runtime.h>
#include <cuda_bf16.h>
#include <cstdint>

// ---------------------------------------------------------------------------
// Shapes: B=2, C=256, Im 768x1280, strides {4,8,16,32}, N=1024 rois
// pool5 D = 256*49 = 12544; fc1: 12544->1024 relu; fc2: 1024->1024 relu; proj->20
// ---------------------------------------------------------------------------

#define NCH 256

// tcgen05 is arch-specific (sm_103a); gate so the baseline compute_103 ptxas
// pass compiles a SIMT fallback instead (driver picks the 103a cubin at run).
#if defined(__CUDA_ARCH__) && defined(__CUDA_ARCH_FEAT_SM103_ALL)
#define HAS_TCGEN05 1
#else
#define HAS_TCGEN05 0
#endif

__device__ float g_nhwc[41779200];
__device__ __nv_bfloat16 g_p5_hi[1024 * 12544];
__device__ __nv_bfloat16 g_p5_lo[1024 * 12544];
__device__ __nv_bfloat16 g_w1_hi[1024 * 12544];
__device__ __nv_bfloat16 g_w1_lo[1024 * 12544];
__device__ __nv_bfloat16 g_fc1_hi[1024 * 1024];
__device__ __nv_bfloat16 g_fc1_lo[1024 * 1024];
__device__ __nv_bfloat16 g_w2_hi[1024 * 1024];
__device__ __nv_bfloat16 g_w2_lo[1024 * 1024];
__device__ float g_fc2[1024 * 1024];

__constant__ size_t c_lvl_off[4] = {0, 31457280, 39321600, 41287680};

// ============================ PTX helpers ==================================
__device__ __forceinline__ uint32_t smem_u32(const void* p) {
    uint32_t a;
    asm("{ .reg .u64 t; cvta.to.shared.u64 t, %1; cvt.u32.u64 %0, t; }" : "=r"(a) : "l"(p));
    return a;
}
__device__ __forceinline__ uint32_t elect_one() {
    uint32_t p;
    asm volatile("{\n\t.reg .pred p;\n\telect.sync _|p, 0xFFFFFFFF;\n\tselp.b32 %0, 1, 0, p;\n\t}" : "=r"(p));
    return p;
}
#define MBARRIER_INIT(addr, cnt) \
    asm volatile("mbarrier.init.shared.b64 [%0], %1;" :: "r"(addr), "r"(cnt) : "memory")
#define MBARRIER_WAIT_PARITY(addr, par) do {                                          \
    uint32_t _m = (addr); uint32_t _p = (par); uint32_t _d;                           \
    asm volatile("{\n\t.reg .pred p;\n\t"                                             \
        "mbarrier.try_wait.parity.acquire.cta.shared::cta.b64 p, [%1], %2;\n\t"       \
        "selp.b32 %0, 1, 0, p;\n\t}" : "=r"(_d) : "r"(_m), "r"(_p) : "memory");       \
    if (!_d) {                                                                        \
        asm volatile("{\n\t.reg .pred P1;\n\t"                                        \
            "WL_%=:\n\t"                                                              \
            "mbarrier.try_wait.parity.acquire.cta.shared::cta.b64 P1, [%0], %1, 0x989680;\n\t" \
            "@P1 bra.uni WD_%=;\n\tbra.uni WL_%=;\n\tWD_%=:\n\t}"                     \
            :: "r"(_m), "r"(_p) : "memory");                                          \
    } } while (0)
#define FENCE_PROXY_ASYNC() asm volatile("fence.proxy.async.shared::cta;" ::: "memory")
#define CP_COMMIT() asm volatile("cp.async.commit_group;" ::: "memory")
#define CP_WAIT_1() asm volatile("cp.async.wait_group 1;" ::: "memory")

#if HAS_TCGEN05
#define TCGEN05_ALLOC(sa, n) \
    asm volatile("tcgen05.alloc.cta_group::1.sync.aligned.shared::cta.b32 [%0], %1;" :: "r"(sa), "r"(n) : "memory")
#define TCGEN05_DEALLOC(t, n) \
    asm volatile("tcgen05.dealloc.cta_group::1.sync.aligned.b32 %0, %1;" :: "r"(t), "r"(n))
#define TCGEN05_RELINQ() \
    asm volatile("tcgen05.relinquish_alloc_permit.cta_group::1.sync.aligned;")
#define TCGEN05_COMMIT(mb) \
    asm volatile("tcgen05.commit.cta_group::1.mbarrier::arrive::one.shared::cluster.b64 [%0];" :: "r"(mb) : "memory")
#define TCGEN05_FENCE_AFTER()  asm volatile("tcgen05.fence::after_thread_sync;" ::: "memory")
#define TCGEN05_FENCE_BEFORE() asm volatile("tcgen05.fence::before_thread_sync;" ::: "memory")
#define TCGEN05_WAIT_LD() asm volatile("tcgen05.wait::ld.sync.aligned;" ::: "memory")

#define TCGEN05_LD_X32(r, ta)                                                          \
    asm volatile("tcgen05.ld.sync.aligned.32x32b.x32.b32 "                             \
        "{%0, %1, %2, %3, %4, %5, %6, %7, %8, %9, %10, %11, %12, %13, %14, %15, "      \
        " %16, %17, %18, %19, %20, %21, %22, %23, %24, %25, %26, %27, %28, %29, %30, %31}, [%32];" \
        : "=r"((r)[0]), "=r"((r)[1]), "=r"((r)[2]), "=r"((r)[3]),                      \
          "=r"((r)[4]), "=r"((r)[5]), "=r"((r)[6]), "=r"((r)[7]),                      \
          "=r"((r)[8]), "=r"((r)[9]), "=r"((r)[10]), "=r"((r)[11]),                    \
          "=r"((r)[12]), "=r"((r)[13]), "=r"((r)[14]), "=r"((r)[15]),                  \
          "=r"((r)[16]), "=r"((r)[17]), "=r"((r)[18]), "=r"((r)[19]),                  \
          "=r"((r)[20]), "=r"((r)[21]), "=r"((r)[22]), "=r"((r)[23]),                  \
          "=r"((r)[24]), "=r"((r)[25]), "=r"((r)[26]), "=r"((r)[27]),                  \
          "=r"((r)[28]), "=r"((r)[29]), "=r"((r)[30]), "=r"((r)[31])                   \
        : "r"(ta))

__device__ __forceinline__ void mma_f16_ss(uint32_t d, uint64_t a, uint64_t b,
                                           uint32_t idesc, bool en) {
    uint32_t e = en ? 1u : 0u;
    asm volatile(
        "{\n\t.reg .pred p;\n\tsetp.ne.u32 p, %4, 0;\n\t"
        "tcgen05.mma.cta_group::1.kind::f16 [%0], %1, %2, %3, {%5, %5, %5, %5}, p;\n\t}"
        :: "r"(d), "l"(a), "l"(b), "r"(idesc), "r"(e), "r"(0u) : "memory");
}
#endif  // HAS_TCGEN05

// SW128 K-major descriptor: layout=2, version=1, SBO=64, LBO=1
static constexpr uint64_t DESC_BASE_SW128 =
    (uint64_t(2) << 61) | (uint64_t(1) << 46) | (uint64_t(64) << 32) | (uint64_t(1) << 16);
#define MAKE_DESC(a) (DESC_BASE_SW128 | ((uint64_t)((a) >> 4) & 0x3FFF))

// idesc kind::f16: F32 accum, BF16 a/b, M=128, N=128
static constexpr uint32_t GEMM_IDESC =
    (1u << 4) | (1u << 7) | (1u << 10) | ((128u / 8u) << 17) | ((128u / 16u) << 24);

__device__ __forceinline__ void pack_hi_lo(float v0, float v1, uint32_t& h, uint32_t& l) {
    asm("cvt.rn.bf16x2.f32 %0, %1, %2;" : "=r"(h) : "f"(v1), "f"(v0));
    float l0 = v0 - __uint_as_float(h << 16);
    float l1 = v1 - __uint_as_float(h & 0xffff0000u);
    asm("cvt.rn.bf16x2.f32 %0, %1, %2;" : "=r"(l) : "f"(l1), "f"(l0));
}

// ---------------------------------------------------------------------------
// NCHW -> NHWC transpose, tiled 32x32
// ---------------------------------------------------------------------------
__global__ void nchw2nhwc_kernel(const float* __restrict__ in, int HW, size_t off) {
    __shared__ float tile[32][33];
    int b = blockIdx.z;
    int hw0 = blockIdx.x * 32;
    int c0 = blockIdx.y * 32;
    const float* ip = in + ((size_t)b * NCH + c0) * HW + hw0;
#pragma unroll
    for (int i = 0; i < 32; i += 8)
        tile[threadIdx.y + i][threadIdx.x] = ip[(size_t)(threadIdx.y + i) * HW + threadIdx.x];
    __syncthreads();
    float* op = g_nhwc + off + ((size_t)b * HW + hw0) * NCH + c0;
#pragma unroll
    for (int i = 0; i < 32; i += 8)
        op[(size_t)(threadIdx.y + i) * NCH + threadIdx.x] = tile[threadIdx.x][threadIdx.y + i];
}

// ---------------------------------------------------------------------------
// ROIAlign: one block per roi, 256 threads = channels; writes hi/lo bf16 rows.
// ---------------------------------------------------------------------------
__global__ void roi_align_kernel(const float* __restrict__ rois) {
    extern __shared__ float shbuf[];  // 12544 floats
    __shared__ int   s_ix0[14], s_ix1[14], s_iy0[14], s_iy1[14];
    __shared__ float s_wx0[14], s_wx1[14], s_wy0[14], s_wy1[14];

    int n = blockIdx.x;
    int tid = threadIdx.x;

    const float* r = rois + (size_t)n * 5;
    int   b  = (int)r[0];
    float x1 = r[1], y1 = r[2], x2 = r[3], y2 = r[4];

    float w = x2 - x1, h = y2 - y1;
    float kf = floorf(4.0f + log2f(sqrtf(fmaxf(w * h, 1e-6f)) / 224.0f));
    kf = fminf(fmaxf(kf, 2.0f), 5.0f);
    int lvl = (int)kf - 2;

    float stride = (float)(4 << lvl);
    int H = 768 >> (lvl + 2);
    int W = 1280 >> (lvl + 2);
    const float* base = g_nhwc + c_lvl_off[lvl] + ((size_t)b * H * W) * NCH;

    if (tid < 28) {
        bool isx = tid < 14;
        int  s   = isx ? tid : tid - 14;
        float lo = isx ? x1 : y1;
        float hi = isx ? x2 : y2;
        int size = isx ? W : H;
        float a = lo / stride - 0.5f;
        float bb = hi / stride - 0.5f;
        float coord = a + (bb - a) * (((float)s + 0.5f) / 14.0f);
        float valid = (coord > -1.0f && coord < (float)size) ? 1.0f : 0.0f;
        float cc = fminf(fmaxf(coord, 0.0f), (float)(size - 1));
        int i0 = (int)floorf(cc);
        int i1 = min(i0 + 1, size - 1);
        float frac = cc - (float)i0;
        if (isx) { s_ix0[s] = i0; s_ix1[s] = i1; s_wx0[s] = (1.0f - frac) * valid; s_wx1[s] = frac * valid; }
        else     { s_iy0[s] = i0; s_iy1[s] = i1; s_wy0[s] = (1.0f - frac) * valid; s_wy1[s] = frac * valid; }
    }
    __syncthreads();

    const float* bc = base + tid;
    for (int by = 0; by < 7; by++) {
        for (int bx = 0; bx < 7; bx++) {
            float acc = 0.0f;
#pragma unroll
            for (int i = 0; i < 2; i++) {
                int sy = by * 2 + i;
                float wy0 = s_wy0[sy], wy1 = s_wy1[sy];
                int row0 = s_iy0[sy] * W;
                int row1 = s_iy1[sy] * W;
#pragma unroll
                for (int j = 0; j < 2; j++) {
                    int sx = bx * 2 + j;
                    float wx0 = s_wx0[sx], wx1 = s_wx1[sx];
                    int xa = s_ix0[sx], xb = s_ix1[sx];
                    float v00 = __ldg(bc + (size_t)(row0 + xa) * NCH);
                    float v01 = __ldg(bc + (size_t)(row0 + xb) * NCH);
                    float v10 = __ldg(bc + (size_t)(row1 + xa) * NCH);
                    float v11 = __ldg(bc + (size_t)(row1 + xb) * NCH);
                    acc += wy0 * (wx0 * v00 + wx1 * v01) + wy1 * (wx0 * v10 + wx1 * v11);
                }
            }
            shbuf[tid * 49 + by * 7 + bx] = acc * 0.25f;
        }
    }
    __syncthreads();

    uint32_t* hd = (uint32_t*)(g_p5_hi + (size_t)n * 12544);
    uint32_t* ld = (uint32_t*)(g_p5_lo + (size_t)n * 12544);
    for (int i = tid; i < 6272; i += 256) {
        float v0 = shbuf[2 * i], v1 = shbuf[2 * i + 1];
        uint32_t hh, ll;
        pack_hi_lo(v0, v1, hh, ll);
        hd[i] = hh; ld[i] = ll;
    }
}

// ---------------------------------------------------------------------------
// fp32 -> bf16 hi/lo split (for weights)
// ---------------------------------------------------------------------------
__global__ void split_kernel(const float* __restrict__ in,
                             __nv_bfloat16* __restrict__ hi,
                             __nv_bfloat16* __restrict__ lo, int n4) {
    int i = blockIdx.x * blockDim.x + threadIdx.x;
    if (i >= n4) return;
    float4 v = ((const float4*)in)[i];
    uint32_t h0, h1, l0, l1;
    pack_hi_lo(v.x, v.y, h0, l0);
    pack_hi_lo(v.z, v.w, h1, l1);
    ((uint2*)hi)[i] = make_uint2(h0, h1);
    ((uint2*)lo)[i] = make_uint2(l0, l1);
}

// ---------------------------------------------------------------------------
// GEMM: C[M,N] = A[M,K] @ B[N,K]^T + bias, ReLU.
// sm_103a: tcgen05, D = Ah*Bh + Ah*Bl + Al*Bh, fp32 TMEM accumulation.
// 128x128 tile, BK=64, 256 threads, cp.async 3-stage pipeline with lagged
// MMA-completion wait (wait MMA i-1 while MMA i runs; refill that stage).
// ---------------------------------------------------------------------------
__device__ __forceinline__ void load_tile16(uint32_t s_tile, const __nv_bfloat16* g,
                                            int ldK, int tid) {
#pragma unroll
    for (int q = 0; q < 4; q++) {
        int gid = tid + q * 256;
        int row = gid >> 3, c16 = gid & 7;
        uint32_t dst = s_tile + row * 128 + ((c16 ^ (row & 7)) << 4);
        const char* src = (const char*)(g + (size_t)row * ldK) + (c16 << 4);
        asm volatile("cp.async.cg.shared.global [%0], [%1], 16;" :: "r"(dst), "l"(src) : "memory");
    }
}

template <bool SPLIT_OUT>
__global__ __launch_bounds__(256, 1) void gemm_tc(
    const __nv_bfloat16* __restrict__ Ahi, const __nv_bfloat16* __restrict__ Alo,
    const __nv_bfloat16* __restrict__ Bhi, const __nv_bfloat16* __restrict__ Blo,
    const float* __restrict__ bias,
    float* __restrict__ Cf, __nv_bfloat16* __restrict__ Chi, __nv_bfloat16* __restrict__ Clo,
    int N, int K) {
    extern __shared__ char dsm[];
    int tid = threadIdx.x;
    int bm = blockIdx.y * 128, bn = blockIdx.x * 128;

#if HAS_TCGEN05
    __shared__ uint32_t s_tmem;
    __shared__ uint64_t s_mbar[3];

    uint32_t sbase = (smem_u32(dsm) + 1023u) & ~1023u;
    int wid = tid >> 5, lid = tid & 31;

    uint32_t mb[3] = { smem_u32(&s_mbar[0]), smem_u32(&s_mbar[1]), smem_u32(&s_mbar[2]) };

    if (wid == 0) TCGEN05_ALLOC(smem_u32(&s_tmem), 128);
    if (tid == 0) { MBARRIER_INIT(mb[0], 1); MBARRIER_INIT(mb[1], 1); MBARRIER_INIT(mb[2], 1); }
    __syncthreads();
    uint32_t tmem = s_tmem;
    if (wid == 0) TCGEN05_RELINQ();

    const int nblk = K >> 6;

    const __nv_bfloat16* Ah = Ahi + (size_t)bm * K;
    const __nv_bfloat16* Al = Alo + (size_t)bm * K;
    const __nv_bfloat16* Bh = Bhi + (size_t)bn * K;
    const __nv_bfloat16* Bl = Blo + (size_t)bn * K;

    // prologue: blocks 0,1 into stages 0,1
#pragma unroll
    for (int p = 0; p < 2; p++) {
        uint32_t st = sbase + (uint32_t)p * 65536u;
        load_tile16(st,          Ah + p * 64, K, tid);
        load_tile16(st + 16384u, Al + p * 64, K, tid);
        load_tile16(st + 32768u, Bh + p * 64, K, tid);
        load_tile16(st + 49152u, Bl + p * 64, K, tid);
        CP_COMMIT();
    }

    int ph[3] = {0, 0, 0};
    int s = 0, sp = 2;  // s = i%3, sp = (i-1)%3
    for (int i = 0; i < nblk; i++) {
        CP_WAIT_1();          // loads for blk i complete (<=1 group pending)
        __syncthreads();
        if (tid < 32) {
            if (elect_one()) {
                FENCE_PROXY_ASYNC();
                uint32_t st = sbase + (uint32_t)s * 65536u;
                uint64_t dah = MAKE_DESC(st);
                uint64_t dal = MAKE_DESC(st + 16384u);
                uint64_t dbh = MAKE_DESC(st + 32768u);
                uint64_t dbl = MAKE_DESC(st + 49152u);
                bool en = (i > 0);
#pragma unroll
                for (int k = 0; k < 4; k++) {
                    mma_f16_ss(tmem, dah + k * 2, dbh + k * 2, GEMM_IDESC, en); en = true;
                    mma_f16_ss(tmem, dah + k * 2, dbl + k * 2, GEMM_IDESC, true);
                    mma_f16_ss(tmem, dal + k * 2, dbh + k * 2, GEMM_IDESC, true);
                }
                TCGEN05_COMMIT(mb[s]);
            }
        }
        // Refill: stage sp (= (i-1)%3) is free once MMA i-1 completed.
        if (i >= 1) {
            MBARRIER_WAIT_PARITY(mb[sp], ph[sp]);
            ph[sp] ^= 1;
            if (i + 2 < nblk) {
                uint32_t st = sbase + (uint32_t)sp * 65536u;
                int j = i + 2;
                load_tile16(st,          Ah + j * 64, K, tid);
                load_tile16(st + 16384u, Al + j * 64, K, tid);
                load_tile16(st + 32768u, Bh + j * 64, K, tid);
                load_tile16(st + 49152u, Bl + j * 64, K, tid);
            }
        } else if (nblk > 2) {
            // i == 0: stage 2 is untouched, load blk 2 now
            uint32_t st = sbase + 2u * 65536u;
            load_tile16(st,          Ah + 2 * 64, K, tid);
            load_tile16(st + 16384u, Al + 2 * 64, K, tid);
            load_tile16(st + 32768u, Bh + 2 * 64, K, tid);
            load_tile16(st + 49152u, Bl + 2 * 64, K, tid);
        }
        CP_COMMIT();          // keep one group per iteration (may be empty)
        sp = s;
        s = (s == 2) ? 0 : s + 1;
    }

    // Wait for the final MMA (completion is in-order: covers all blocks).
    {
        int lastS = (nblk - 1) % 3;
        MBARRIER_WAIT_PARITY(mb[lastS], ph[lastS]);
    }
    TCGEN05_FENCE_AFTER();

    if (tid < 128) {
        int row = bm + wid * 32 + lid;
#pragma unroll
        for (int cb = 0; cb < 128; cb += 32) {
            uint32_t rr[32];
            TCGEN05_LD_X32(rr, tmem + cb);
            TCGEN05_WAIT_LD();
            if (SPLIT_OUT) {
                uint32_t* hd = (uint32_t*)(Chi + (size_t)row * N + bn + cb);
                uint32_t* ld = (uint32_t*)(Clo + (size_t)row * N + bn + cb);
#pragma unroll
                for (int c = 0; c < 32; c += 2) {
                    float v0 = fmaxf(__uint_as_float(rr[c])     + bias[bn + cb + c],     0.0f);
                    float v1 = fmaxf(__uint_as_float(rr[c + 1]) + bias[bn + cb + c + 1], 0.0f);
                    uint32_t hh, ll;
                    pack_hi_lo(v0, v1, hh, ll);
                    hd[c >> 1] = hh; ld[c >> 1] = ll;
                }
            } else {
                float* cd = Cf + (size_t)row * N + bn + cb;
#pragma unroll
                for (int c = 0; c < 32; c++)
                    cd[c] = fmaxf(__uint_as_float(rr[c]) + bias[bn + cb + c], 0.0f);
            }
        }
        TCGEN05_FENCE_BEFORE();
    }
    __syncthreads();
    if (wid == 0) TCGEN05_DEALLOC(tmem, 128);

#else  // ---------------- SIMT fallback (baseline compute_103 pass) ---------
    float* As = (float*)dsm;
    float* Bs = As + 16 * 132;

    int tr = (tid >> 4) * 8;
    int tc = (tid & 15) * 8;

    float acc[8][8] = {};

    for (int k0 = 0; k0 < K; k0 += 16) {
#pragma unroll
        for (int e = 0; e < 8; e++) {
            int idx = tid * 8 + e;
            int kk = idx >> 7, rr = idx & 127;
            As[kk * 132 + rr] = __bfloat162float(Ahi[(size_t)(bm + rr) * K + k0 + kk]) +
                                __bfloat162float(Alo[(size_t)(bm + rr) * K + k0 + kk]);
            Bs[kk * 132 + rr] = __bfloat162float(Bhi[(size_t)(bn + rr) * K + k0 + kk]) +
                                __bfloat162float(Blo[(size_t)(bn + rr) * K + k0 + kk]);
        }
        __syncthreads();
#pragma unroll
        for (int k = 0; k < 16; k++) {
            float ra[8], rb[8];
#pragma unroll
            for (int i = 0; i < 8; i++) ra[i] = As[k * 132 + tr + i];
#pragma unroll
            for (int j = 0; j < 8; j++) rb[j] = Bs[k * 132 + tc + j];
#pragma unroll
            for (int i = 0; i < 8; i++)
#pragma unroll
                for (int j = 0; j < 8; j++) acc[i][j] += ra[i] * rb[j];
        }
        __syncthreads();
    }

#pragma unroll
    for (int i = 0; i < 8; i++) {
#pragma unroll
        for (int j = 0; j < 8; j += 2) {
            float v0 = fmaxf(acc[i][j]     + bias[bn + tc + j],     0.0f);
            float v1 = fmaxf(acc[i][j + 1] + bias[bn + tc + j + 1], 0.0f);
            size_t o = (size_t)(bm + tr + i) * N + bn + tc + j;
            if (SPLIT_OUT) {
                uint32_t hh, ll;
                pack_hi_lo(v0, v1, hh, ll);
                *(uint32_t*)(Chi + o) = hh;
                *(uint32_t*)(Clo + o) = ll;
            } else {
                Cf[o] = v0; Cf[o + 1] = v1;
            }
        }
    }
#endif
}

// ---------------------------------------------------------------------------
// Final projection: out[n, j] = dot(fc2[n,:], p_w[j,:]) + p_b[j], j < 20
// ---------------------------------------------------------------------------
__global__ void proj_kernel(const float* __restrict__ fc2,
                            const float* __restrict__ p_w,
                            const float* __restrict__ p_b,
                            float* __restrict__ out, int NJ) {
    __shared__ float sh[1024];
    int n = blockIdx.x;
    for (int i = threadIdx.x; i < 1024; i += blockDim.x)
        sh[i] = fc2[(size_t)n * 1024 + i];
    __syncthreads();
    int j = threadIdx.x;
    if (j < NJ) {
        const float* wrow = p_w + (size_t)j * 1024;
        float s = p_b[j];
#pragma unroll 8
        for (int k = 0; k < 1024; k++) s += sh[k] * wrow[k];
        out[(size_t)n * NJ + j] = s;
    }
}

// ---------------------------------------------------------------------------
extern "C" void kernel_launch(void* const* d_in, const int* in_sizes, int n_in,
                              void* d_out, int out_size) {
    const float* fm0   = (const float*)d_in[0];
    const float* fm1   = (const float*)d_in[1];
    const float* fm2   = (const float*)d_in[2];
    const float* fm3   = (const float*)d_in[3];
    const float* rois  = (const float*)d_in[4];
    const float* fc1_w = (const float*)d_in[5];
    const float* fc1_b = (const float*)d_in[6];
    const float* fc2_w = (const float*)d_in[7];
    const float* fc2_b = (const float*)d_in[8];
    const float* p_w   = (const float*)d_in[9];
    const float* p_b   = (const float*)d_in[10];
    float* out = (float*)d_out;

    int nrois = in_sizes[4] / 5;   // 1024
    int nj = out_size / nrois;     // 20

    // Side stream for the weight splits (created once; fork/join via events
    // so the work is part of the captured graph).
    static cudaStream_t s2 = nullptr;
    static cudaEvent_t evF = nullptr, evJ = nullptr;
    if (!s2) {
        cudaStreamCreateWithFlags(&s2, cudaStreamNonBlocking);
        cudaEventCreateWithFlags(&evF, cudaEventDisableTiming);
        cudaEventCreateWithFlags(&evJ, cudaEventDisableTiming);
    }

    __nv_bfloat16 *w1h, *w1l, *w2h, *w2l, *p5h, *p5l, *f1h, *f1l;
    float* fc2p;
    cudaGetSymbolAddress((void**)&w1h, g_w1_hi);
    cudaGetSymbolAddress((void**)&w1l, g_w1_lo);
    cudaGetSymbolAddress((void**)&w2h, g_w2_hi);
    cudaGetSymbolAddress((void**)&w2l, g_w2_lo);
    cudaGetSymbolAddress((void**)&p5h, g_p5_hi);
    cudaGetSymbolAddress((void**)&p5l, g_p5_lo);
    cudaGetSymbolAddress((void**)&f1h, g_fc1_hi);
    cudaGetSymbolAddress((void**)&f1l, g_fc1_lo);
    cudaGetSymbolAddress((void**)&fc2p, g_fc2);

    // Fork: weight splits run concurrent with transposes + ROI.
    cudaEventRecord(evF, 0);
    cudaStreamWaitEvent(s2, evF, 0);
    split_kernel<<<(12544 * 1024 / 4 + 255) / 256, 256, 0, s2>>>(fc1_w, w1h, w1l, 12544 * 1024 / 4);
    split_kernel<<<(1024 * 1024 / 4 + 255) / 256, 256, 0, s2>>>(fc2_w, w2h, w2l, 1024 * 1024 / 4);
    cudaEventRecord(evJ, s2);

    // Main stream: NCHW -> NHWC, then ROIAlign -> pool5 (bf16 hi/lo)
    nchw2nhwc_kernel<<<dim3(61440 / 32, 8, 2), dim3(32, 8)>>>(fm0, 61440, (size_t)0);
    nchw2nhwc_kernel<<<dim3(15360 / 32, 8, 2), dim3(32, 8)>>>(fm1, 15360, (size_t)31457280);
    nchw2nhwc_kernel<<<dim3(3840 / 32, 8, 2), dim3(32, 8)>>>(fm2, 3840, (size_t)39321600);
    nchw2nhwc_kernel<<<dim3(960 / 32, 8, 2), dim3(32, 8)>>>(fm3, 960, (size_t)41287680);

    cudaFuncSetAttribute(roi_align_kernel,
                         cudaFuncAttributeMaxDynamicSharedMemorySize, 50176);
    roi_align_kernel<<<nrois, 256, 50176>>>(rois);

    // Join before the GEMMs need the split weights.
    cudaStreamWaitEvent(0, evJ, 0);

    const int GEMM_SMEM = 1024 + 3 * 65536;  // 197632 (3-stage)
    cudaFuncSetAttribute(gemm_tc<true>,
                         cudaFuncAttributeMaxDynamicSharedMemorySize, GEMM_SMEM);
    cudaFuncSetAttribute(gemm_tc<false>,
                         cudaFuncAttributeMaxDynamicSharedMemorySize, GEMM_SMEM);

    // FC1: [1024, 12544] x [1024, 12544]^T -> fc1 hi/lo
    gemm_tc<true><<<dim3(8, nrois / 128), 256, GEMM_SMEM>>>(
        p5h, p5l, w1h, w1l, fc1_b, nullptr, f1h, f1l, 1024, 12544);
    // FC2: [1024, 1024] x [1024, 1024]^T -> fc2 fp32
    gemm_tc<false><<<dim3(8, nrois / 128), 256, GEMM_SMEM>>>(
        f1h, f1l, w2h, w2l, fc2_b, fc2p, nullptr, nullptr, 1024, 1024);

    // Projection
    proj_kernel<<<nrois, 256>>>(fc2p, p_w, p_b, out, nj);
}